// round 6
// baseline (speedup 1.0000x reference)
#include <cuda_runtime.h>
#include <cuda_fp16.h>
#include <stdint.h>

// ---------------------------------------------------------------------------
// Problem constants
// ---------------------------------------------------------------------------
#define N_TOK 65536
#define DIM   1024
#define S_SEM 200
#define NPACK 352      // 1 cls + 12 fused-sem + 324 bbox + 15 zero pad
#define NSC   81
#define NBB   324
#define BM    128
#define BN    176      // N-split: 2 CTAs per M-tile
#define BK    64
#define NKCH  (DIM / BK)     // 16
#define THREADS 256
#define AROWF 68             // A32 smem row: 64 floats + 4 pad (272B, 16B-aligned)

// Packed fp16 weights + fp32 bias (built by prep kernel every launch)
__device__ __half g_Wp[NPACK * DIM];
__device__ float  g_bp[NPACK];

// Selected class indices (0-based into the 80 class cols): {i-1 : i in IGNORE2} U {79}
__constant__ int c_sel[12] = {1, 2, 16, 18, 29, 37, 47, 53, 63, 68, 72, 79};

__device__ __forceinline__ constexpr bool cls_keep(int j) {
    return j == 1 || j == 2 || j == 16 || j == 18 || j == 29 || j == 37 ||
           j == 47 || j == 53 || j == 63 || j == 68 || j == 72 || j == 79;
}

__device__ __forceinline__ uint32_t smem_u32(const void* p) {
    uint32_t a;
    asm("{ .reg .u64 t; cvta.to.shared.u64 t, %1; cvt.u32.u64 %0, t; }"
        : "=r"(a) : "l"(p));
    return a;
}

// ---------------------------------------------------------------------------
// SMEM layout (bytes) — 97792 total => 2 CTAs resident per SM
// ---------------------------------------------------------------------------
#define SMO_BIAS 0                               // 1536
#define SMO_A32  1536                            // 128 x 272B = 34816 (1 buf)
#define SMO_A16  (SMO_A32 + BM * AROWF * 4)      // 36352; 128 x 128B = 16384 (1 buf)
#define SMO_B    (SMO_A16 + BM * 128)            // 52736; 2 x 176 x 128B = 45056
#define SM_TOTAL (SMO_B + 2 * BN * 128)          // 97792

// ---------------------------------------------------------------------------
// Prep: pack [W_cls ; sem_matrix[sel] @ W_sem / S ; W_bbox ; 0-pad] -> fp16
// ---------------------------------------------------------------------------
#define SEM_BLKS 48
__global__ void prep_kernel(const float* __restrict__ W_cls,
                            const float* __restrict__ b_cls,
                            const float* __restrict__ W_sem,
                            const float* __restrict__ b_sem,
                            const float* __restrict__ W_bbox,
                            const float* __restrict__ b_bbox,
                            const float* __restrict__ sem_m) {
    const int tid = threadIdx.x;
    const int bid = blockIdx.x;
    if (bid < SEM_BLKS) {
        __shared__ float sM[S_SEM];
        const int r = (bid >> 2) + 1;            // packed row 1..12
        const int chunk = bid & 3;
        const int sj = c_sel[r - 1];
        const float* M = sem_m + (size_t)sj * S_SEM;
        if (tid < S_SEM) sM[tid] = M[tid];
        __syncthreads();
        const int d = chunk * 256 + tid;
        const float* Wcol = W_sem + d;
        float a0 = 0.f, a1 = 0.f, a2 = 0.f, a3 = 0.f;
#pragma unroll 4
        for (int s = 0; s < S_SEM; s += 4) {
            a0 += sM[s + 0] * Wcol[(size_t)(s + 0) * DIM];
            a1 += sM[s + 1] * Wcol[(size_t)(s + 1) * DIM];
            a2 += sM[s + 2] * Wcol[(size_t)(s + 2) * DIM];
            a3 += sM[s + 3] * Wcol[(size_t)(s + 3) * DIM];
        }
        g_Wp[(size_t)r * DIM + d] = __float2half(((a0 + a1) + (a2 + a3)) * (1.0f / S_SEM));
        if (chunk == 0 && tid < 32) {
            float p = 0.f;
            for (int s = tid; s < S_SEM; s += 32) p += sM[s] * b_sem[s];
#pragma unroll
            for (int o = 16; o > 0; o >>= 1) p += __shfl_xor_sync(0xffffffffu, p, o);
            if (tid == 0) g_bp[r] = p * (1.0f / S_SEM);
        }
    } else {
        const int r = bid - SEM_BLKS;            // 0..351
        if (r >= 1 && r <= 12) return;           // sem blocks own these
        __half* dst = g_Wp + (size_t)r * DIM;
        if (r == 0) {
            float4 v = ((const float4*)W_cls)[tid];
            ((__half2*)dst)[tid * 2 + 0] = __floats2half2_rn(v.x, v.y);
            ((__half2*)dst)[tid * 2 + 1] = __floats2half2_rn(v.z, v.w);
            if (tid == 0) g_bp[0] = b_cls[0];
        } else if (r < 13 + NBB) {
            const int c = r - 13;
            float4 v = ((const float4*)(W_bbox + (size_t)c * DIM))[tid];
            ((__half2*)dst)[tid * 2 + 0] = __floats2half2_rn(v.x, v.y);
            ((__half2*)dst)[tid * 2 + 1] = __floats2half2_rn(v.z, v.w);
            if (tid == 0) g_bp[r] = b_bbox[c];
        } else {
            ((__half2*)dst)[tid * 2 + 0] = __floats2half2_rn(0.f, 0.f);
            ((__half2*)dst)[tid * 2 + 1] = __floats2half2_rn(0.f, 0.f);
            if (tid == 0) g_bp[r] = 0.0f;
        }
    }
}

// ---------------------------------------------------------------------------
// Main GEMM: per CTA [128, 1024] x [1024, 176] via mma.sync m16n8k16 fp16.
// Grid 1024: blockIdx>>1 = M-tile, blockIdx&1 = N-half. 2 CTAs/SM.
// ---------------------------------------------------------------------------
__global__ void __launch_bounds__(THREADS, 2)
fpn_gemm(const float* __restrict__ x, float* __restrict__ out) {
    extern __shared__ char smem[];
    float* s_bias = (float*)(smem + SMO_BIAS);
    float* sA32 = (float*)(smem + SMO_A32);
    const uint32_t sbA32 = smem_u32(smem + SMO_A32);
    const uint32_t sbA16 = smem_u32(smem + SMO_A16);
    const uint32_t sbB   = smem_u32(smem + SMO_B);

    const int tid = threadIdx.x;
    const int wid = tid >> 5, lid = tid & 31;
    const int wm = wid >> 1, wn = wid & 1;        // 4 warps M x 2 warps N
    const int mbase  = (blockIdx.x >> 1) * BM;
    const int nsplit = blockIdx.x & 1;
    const int q = lid >> 2, t = lid & 3;

    for (int i = tid; i < NPACK; i += THREADS) s_bias[i] = g_bp[i];

    float acc[2][11][4];
#pragma unroll
    for (int a = 0; a < 2; a++)
#pragma unroll
        for (int b = 0; b < 11; b++)
#pragma unroll
            for (int e = 0; e < 4; e++) acc[a][b][e] = 0.0f;

    // --- stage chunk kc: A32 (single buf) + B (double buf) via cp.async ---
    auto stage = [&](int kc) {
        if (kc < NKCH) {
            const char* xs = (const char*)(x + (size_t)mbase * DIM + kc * BK);
#pragma unroll
            for (int it = 0; it < 8; it++) {
                int i = it * THREADS + tid;       // 0..2047
                int r = i >> 4, j = i & 15;
                uint32_t d = sbA32 + r * (AROWF * 4) + j * 16;
                const char* s = xs + (size_t)r * (DIM * 4) + j * 16;
                asm volatile("cp.async.cg.shared.global [%0], [%1], 16;" :: "r"(d), "l"(s));
            }
            const char* ws = (const char*)(g_Wp + (size_t)nsplit * BN * DIM)
                             + (size_t)kc * (BK * 2);
            const uint32_t bdst = sbB + (kc & 1) * (BN * 128);
#pragma unroll
            for (int it = 0; it < 6; it++) {
                int i = it * THREADS + tid;       // 0..1407 (guarded)
                if (it < 5 || i < BN * 8) {
                    int r = i >> 3, j = i & 7;
                    uint32_t off = (uint32_t)(r * 128 + j * 16);
                    uint32_t d = bdst + (off ^ ((off >> 3) & 0x70));
                    const char* s = ws + (size_t)r * (DIM * 2) + j * 16;
                    asm volatile("cp.async.cg.shared.global [%0], [%1], 16;"
                                 :: "r"(d), "l"(s));
                }
            }
        }
        asm volatile("cp.async.commit_group;" ::: "memory");
    };

    stage(0);

    for (int kc = 0; kc < NKCH; kc++) {
        asm volatile("cp.async.wait_group 0;" ::: "memory");   // A32(kc), B(kc) ready
        __syncthreads();            // also guards A16 WAR vs MMA(kc-1)

        // ---- convert A32 -> A16 (SW128 swizzled): 2 threads/row, 32 f32 each ----
        {
            const int r = tid >> 1, h = tid & 1;
            const float* src = sA32 + r * AROWF + h * 32;
            char* adst = smem + SMO_A16;
#pragma unroll
            for (int i2 = 0; i2 < 2; i2++) {
                float4 v0 = *(const float4*)(src + i2 * 16 + 0);
                float4 v1 = *(const float4*)(src + i2 * 16 + 4);
                float4 v2 = *(const float4*)(src + i2 * 16 + 8);
                float4 v3 = *(const float4*)(src + i2 * 16 + 12);
                uint4 w0, w1;
                union { __half2 h2; uint32_t u; } p;
                p.h2 = __floats2half2_rn(v0.x, v0.y); w0.x = p.u;
                p.h2 = __floats2half2_rn(v0.z, v0.w); w0.y = p.u;
                p.h2 = __floats2half2_rn(v1.x, v1.y); w0.z = p.u;
                p.h2 = __floats2half2_rn(v1.z, v1.w); w0.w = p.u;
                p.h2 = __floats2half2_rn(v2.x, v2.y); w1.x = p.u;
                p.h2 = __floats2half2_rn(v2.z, v2.w); w1.y = p.u;
                p.h2 = __floats2half2_rn(v3.x, v3.y); w1.z = p.u;
                p.h2 = __floats2half2_rn(v3.z, v3.w); w1.w = p.u;
                uint32_t o0 = (uint32_t)(r * 128 + h * 64 + i2 * 32);
                uint32_t o1 = o0 + 16;
                *(uint4*)(adst + (o0 ^ ((o0 >> 3) & 0x70))) = w0;
                *(uint4*)(adst + (o1 ^ ((o1 >> 3) & 0x70))) = w1;
            }
        }
        __syncthreads();            // A16 visible; A32/B(kc+1 buf) safe to overwrite
        stage(kc + 1);              // overlap next chunk loads with MMA(kc)

        const uint32_t Bbuf = sbB + (kc & 1) * (BN * 128);

#pragma unroll
        for (int ks = 0; ks < 4; ks++) {
            // ---- A fragments via ldmatrix.x4 ----
            uint32_t af[2][4];
#pragma unroll
            for (int mf = 0; mf < 2; mf++) {
                uint32_t row = (uint32_t)(wm * 32 + mf * 16 + (lid & 15));
                uint32_t off = row * 128 + (uint32_t)(ks * 32 + ((lid >> 4) & 1) * 16);
                uint32_t addr = sbA16 + (off ^ ((off >> 3) & 0x70));
                asm volatile("ldmatrix.sync.aligned.m8n8.x4.shared.b16 {%0,%1,%2,%3}, [%4];"
                             : "=r"(af[mf][0]), "=r"(af[mf][1]),
                               "=r"(af[mf][2]), "=r"(af[mf][3]) : "r"(addr));
            }
            // ---- B fragments: x4 covers two adjacent n-frags ----
#pragma unroll
            for (int np = 0; np < 5; np++) {
                const int nf = np * 2;
                int row = wn * 88 + (nf + ((lid >> 4) & 1)) * 8 + (lid & 7);
                uint32_t off = (uint32_t)(row * 128 + ks * 32 + ((lid >> 3) & 1) * 16);
                uint32_t addr = Bbuf + (off ^ ((off >> 3) & 0x70));
                uint32_t b0, b1, b2, b3;
                asm volatile("ldmatrix.sync.aligned.m8n8.x4.shared.b16 {%0,%1,%2,%3}, [%4];"
                             : "=r"(b0), "=r"(b1), "=r"(b2), "=r"(b3) : "r"(addr));
#pragma unroll
                for (int mf = 0; mf < 2; mf++) {
                    asm volatile(
                        "mma.sync.aligned.m16n8k16.row.col.f32.f16.f16.f32 "
                        "{%0,%1,%2,%3},{%4,%5,%6,%7},{%8,%9},{%0,%1,%2,%3};"
                        : "+f"(acc[mf][nf][0]), "+f"(acc[mf][nf][1]),
                          "+f"(acc[mf][nf][2]), "+f"(acc[mf][nf][3])
                        : "r"(af[mf][0]), "r"(af[mf][1]), "r"(af[mf][2]), "r"(af[mf][3]),
                          "r"(b0), "r"(b1));
                    asm volatile(
                        "mma.sync.aligned.m16n8k16.row.col.f32.f16.f16.f32 "
                        "{%0,%1,%2,%3},{%4,%5,%6,%7},{%8,%9},{%0,%1,%2,%3};"
                        : "+f"(acc[mf][nf + 1][0]), "+f"(acc[mf][nf + 1][1]),
                          "+f"(acc[mf][nf + 1][2]), "+f"(acc[mf][nf + 1][3])
                        : "r"(af[mf][0]), "r"(af[mf][1]), "r"(af[mf][2]), "r"(af[mf][3]),
                          "r"(b2), "r"(b3));
                }
            }
            {   // ---- last n-frag (nf = 10), x2 ----
                const int nf = 10;
                int row = wn * 88 + nf * 8 + (lid & 7);
                uint32_t off = (uint32_t)(row * 128 + ks * 32 + ((lid >> 3) & 1) * 16);
                uint32_t addr = Bbuf + (off ^ ((off >> 3) & 0x70));
                uint32_t b0, b1;
                asm volatile("ldmatrix.sync.aligned.m8n8.x2.shared.b16 {%0,%1}, [%2];"
                             : "=r"(b0), "=r"(b1) : "r"(addr));
#pragma unroll
                for (int mf = 0; mf < 2; mf++) {
                    asm volatile(
                        "mma.sync.aligned.m16n8k16.row.col.f32.f16.f16.f32 "
                        "{%0,%1,%2,%3},{%4,%5,%6,%7},{%8,%9},{%0,%1,%2,%3};"
                        : "+f"(acc[mf][nf][0]), "+f"(acc[mf][nf][1]),
                          "+f"(acc[mf][nf][2]), "+f"(acc[mf][nf][3])
                        : "r"(af[mf][0]), "r"(af[mf][1]), "r"(af[mf][2]), "r"(af[mf][3]),
                          "r"(b0), "r"(b1));
                }
            }
        }
    }

    // ---- zero the 68 masked class-score columns (first N-half CTAs only) ----
    if (nsplit == 0) {
        int r = tid >> 1, sub = tid & 1;
        float* srow = out + (size_t)(mbase + r) * NSC;
#pragma unroll
        for (int j = sub; j < 80; j += 2)
            if (!cls_keep(j)) srow[1 + j] = 0.0f;
    }

    // ---- scatter accumulators (+bias) ----
    const int cbase = nsplit * BN + wn * 88;
#pragma unroll
    for (int mf = 0; mf < 2; mf++) {
#pragma unroll
        for (int half = 0; half < 2; half++) {
            const int m = mbase + wm * 32 + mf * 16 + q + half * 8;
            float* srow = out + (size_t)m * NSC;
            float* brow = out + (size_t)N_TOK * NSC + (size_t)m * NBB;
#pragma unroll
            for (int nf = 0; nf < 11; nf++) {
#pragma unroll
                for (int e = 0; e < 2; e++) {
                    const int c = cbase + nf * 8 + t * 2 + e;
                    float v = acc[mf][nf][half * 2 + e] + s_bias[c];
                    if (c == 0)        srow[0] = v;
                    else if (c <= 12)  srow[1 + c_sel[c - 1]] = v;
                    else if (c <= 336) brow[c - 13] = v;
                }
            }
        }
    }
}

// ---------------------------------------------------------------------------
// Launch
// ---------------------------------------------------------------------------
extern "C" void kernel_launch(void* const* d_in, const int* in_sizes, int n_in,
                              void* d_out, int out_size) {
    const float* x      = (const float*)d_in[0];
    const float* W_cls  = (const float*)d_in[1];
    const float* b_cls  = (const float*)d_in[2];
    const float* W_sem  = (const float*)d_in[3];
    const float* b_sem  = (const float*)d_in[4];
    const float* W_bbox = (const float*)d_in[5];
    const float* b_bbox = (const float*)d_in[6];
    const float* sem_m  = (const float*)d_in[7];
    float* out = (float*)d_out;

    cudaFuncSetAttribute(fpn_gemm, cudaFuncAttributeMaxDynamicSharedMemorySize, SM_TOTAL);

    prep_kernel<<<SEM_BLKS + NPACK, 256>>>(W_cls, b_cls, W_sem, b_sem, W_bbox, b_bbox, sem_m);
    fpn_gemm<<<(N_TOK / BM) * 2, THREADS, SM_TOTAL>>>(x, out);
}